// round 15
// baseline (speedup 1.0000x reference)
#include <cuda_runtime.h>
#include <cuda_bf16.h>
#include <stdint.h>

#define N_NODES 50000
#define N_EDGES 1600000
#define F 256
#define OUTF 64

// ---------------- scratch (static device globals; no runtime alloc) ----------
__device__ float g_h1[(long)N_NODES * F];    // layer-0 output
__device__ float g_ys[(long)N_NODES * F];    // self-term buffer
__device__ float g_yn[(long)N_NODES * F];    // neighbor-term fp32 (layer 2)
__device__ __nv_bfloat16 g_ynb[(long)N_NODES * F];  // neighbor-term bf16 (layers 0/1)
__device__ int   g_rowptr[N_NODES + 1];
__device__ int   g_cursor[N_NODES];
__device__ int   g_col[N_EDGES];
__device__ int   g_deg[N_NODES];
__device__ float g_invdeg[N_NODES];

// ---------------- CSR build ---------------------------------------------------
__global__ void count_kernel(const int* __restrict__ dst) {
    int e = blockIdx.x * blockDim.x + threadIdx.x;
    if (e < N_EDGES) atomicAdd(&g_deg[dst[e]], 1);
}

__global__ __launch_bounds__(1024) void scan_kernel() {
    __shared__ int sm[1024];
    const int CH = (N_NODES + 1023) / 1024;
    int tid = threadIdx.x;
    int start = tid * CH;
    int end = min(start + CH, N_NODES);
    int local = 0;
    for (int i = start; i < end; i++) local += g_deg[i];
    sm[tid] = local;
    __syncthreads();
    #pragma unroll
    for (int off = 1; off < 1024; off <<= 1) {
        int t = (tid >= off) ? sm[tid - off] : 0;
        __syncthreads();
        sm[tid] += t;
        __syncthreads();
    }
    int run = sm[tid] - local;
    for (int i = start; i < end; i++) {
        int v = g_deg[i];
        g_rowptr[i] = run;
        g_cursor[i] = run;
        g_invdeg[i] = 1.0f / (float)max(v, 1);
        run += v;
    }
    if (tid == 0) g_rowptr[N_NODES] = sm[1023];
}

__global__ void fill_kernel(const int* __restrict__ src, const int* __restrict__ dst) {
    int e = blockIdx.x * blockDim.x + threadIdx.x;
    if (e < N_EDGES) {
        int d = dst[e];
        int p = atomicAdd(&g_cursor[d], 1);
        g_col[p] = src[e];
    }
}

// ---------------- SpMM fp32 (layer 2): out = ys + invdeg * sum yn[src] --------
template<int L4, bool RELU>
__global__ __launch_bounds__(256) void spmm_add_kernel(
    const float4* __restrict__ yn, const float4* __restrict__ ys,
    float4* __restrict__ out)
{
    constexpr int NPB = 256 / L4;
    int group = threadIdx.x / L4;
    int lane  = threadIdx.x % L4;
    int n = blockIdx.x * NPB + group;
    if (n >= N_NODES) return;
    int s = g_rowptr[n];
    int e = g_rowptr[n + 1];

    float4 a0 = make_float4(0.f, 0.f, 0.f, 0.f);
    float4 a1 = a0, a2 = a0, a3 = a0;
    float4 a4 = a0, a5 = a0, a6 = a0, a7 = a0;

    int i = s;
    int alignEnd = min(e, (s + 3) & ~3);
    for (; i < alignEnd; i++) {
        int c = __ldg(&g_col[i]);
        float4 v = yn[(long)c * L4 + lane];
        a0.x += v.x; a0.y += v.y; a0.z += v.z; a0.w += v.w;
    }
    for (; i + 8 <= e; i += 8) {
        int4 c0 = *(const int4*)&g_col[i];
        int4 c1 = *(const int4*)&g_col[i + 4];
        float4 v0 = yn[(long)c0.x * L4 + lane];
        float4 v1 = yn[(long)c0.y * L4 + lane];
        float4 v2 = yn[(long)c0.z * L4 + lane];
        float4 v3 = yn[(long)c0.w * L4 + lane];
        float4 v4 = yn[(long)c1.x * L4 + lane];
        float4 v5 = yn[(long)c1.y * L4 + lane];
        float4 v6 = yn[(long)c1.z * L4 + lane];
        float4 v7 = yn[(long)c1.w * L4 + lane];
        a0.x += v0.x; a0.y += v0.y; a0.z += v0.z; a0.w += v0.w;
        a1.x += v1.x; a1.y += v1.y; a1.z += v1.z; a1.w += v1.w;
        a2.x += v2.x; a2.y += v2.y; a2.z += v2.z; a2.w += v2.w;
        a3.x += v3.x; a3.y += v3.y; a3.z += v3.z; a3.w += v3.w;
        a4.x += v4.x; a4.y += v4.y; a4.z += v4.z; a4.w += v4.w;
        a5.x += v5.x; a5.y += v5.y; a5.z += v5.z; a5.w += v5.w;
        a6.x += v6.x; a6.y += v6.y; a6.z += v6.z; a6.w += v6.w;
        a7.x += v7.x; a7.y += v7.y; a7.z += v7.z; a7.w += v7.w;
    }
    for (; i + 4 <= e; i += 4) {
        int4 c = *(const int4*)&g_col[i];
        float4 v0 = yn[(long)c.x * L4 + lane];
        float4 v1 = yn[(long)c.y * L4 + lane];
        float4 v2 = yn[(long)c.z * L4 + lane];
        float4 v3 = yn[(long)c.w * L4 + lane];
        a0.x += v0.x; a0.y += v0.y; a0.z += v0.z; a0.w += v0.w;
        a1.x += v1.x; a1.y += v1.y; a1.z += v1.z; a1.w += v1.w;
        a2.x += v2.x; a2.y += v2.y; a2.z += v2.z; a2.w += v2.w;
        a3.x += v3.x; a3.y += v3.y; a3.z += v3.z; a3.w += v3.w;
    }
    for (; i < e; i++) {
        int c = __ldg(&g_col[i]);
        float4 v = yn[(long)c * L4 + lane];
        a0.x += v.x; a0.y += v.y; a0.z += v.z; a0.w += v.w;
    }

    float d = g_invdeg[n];
    float4 sv = ys[(long)n * L4 + lane];
    float4 r;
    r.x = sv.x + ((a0.x + a1.x) + (a2.x + a3.x) + (a4.x + a5.x) + (a6.x + a7.x)) * d;
    r.y = sv.y + ((a0.y + a1.y) + (a2.y + a3.y) + (a4.y + a5.y) + (a6.y + a7.y)) * d;
    r.z = sv.z + ((a0.z + a1.z) + (a2.z + a3.z) + (a4.z + a5.z) + (a6.z + a7.z)) * d;
    r.w = sv.w + ((a0.w + a1.w) + (a2.w + a3.w) + (a4.w + a5.w) + (a6.w + a7.w)) * d;
    if (RELU) {
        r.x = fmaxf(r.x, 0.f); r.y = fmaxf(r.y, 0.f);
        r.z = fmaxf(r.z, 0.f); r.w = fmaxf(r.w, 0.f);
    }
    out[(long)n * L4 + lane] = r;
}

// ---------------- SpMM bf16 gather (layers 0/1, 256-dim) ----------------------
// 8-edge-deep gather: 8 independent uint4 LDG.128 in flight per thread so the
// L2 round-trip is latency-hidden (MLP_eff 4 -> 8) and the LTS cap binds.
__device__ __forceinline__ void acc_bf16x2(float* a, unsigned u) {
    a[0] += __uint_as_float(u << 16);
    a[1] += __uint_as_float(u & 0xffff0000u);
}
__device__ __forceinline__ void acc_u4(float* a, uint4 v) {
    acc_bf16x2(a + 0, v.x);
    acc_bf16x2(a + 2, v.y);
    acc_bf16x2(a + 4, v.z);
    acc_bf16x2(a + 6, v.w);
}

template<bool RELU>
__global__ __launch_bounds__(256) void spmm_bf16_kernel(
    const uint4* __restrict__ ynb, const float4* __restrict__ ys,
    float4* __restrict__ out)
{
    int group = threadIdx.x >> 5;
    int lane  = threadIdx.x & 31;       // 32 x 16B = 512B = 256 bf16
    int n = blockIdx.x * 8 + group;
    if (n >= N_NODES) return;
    int s = g_rowptr[n];
    int e = g_rowptr[n + 1];

    float a[8];
    #pragma unroll
    for (int j = 0; j < 8; j++) a[j] = 0.f;

    int i = s;
    int alignEnd = min(e, (s + 3) & ~3);
    for (; i < alignEnd; i++) {
        int c = __ldg(&g_col[i]);
        acc_u4(a, ynb[(long)c * 32 + lane]);
    }
    for (; i + 8 <= e; i += 8) {
        int4 c0 = *(const int4*)&g_col[i];
        int4 c1 = *(const int4*)&g_col[i + 4];
        uint4 v0 = ynb[(long)c0.x * 32 + lane];
        uint4 v1 = ynb[(long)c0.y * 32 + lane];
        uint4 v2 = ynb[(long)c0.z * 32 + lane];
        uint4 v3 = ynb[(long)c0.w * 32 + lane];
        uint4 v4 = ynb[(long)c1.x * 32 + lane];
        uint4 v5 = ynb[(long)c1.y * 32 + lane];
        uint4 v6 = ynb[(long)c1.z * 32 + lane];
        uint4 v7 = ynb[(long)c1.w * 32 + lane];
        acc_u4(a, v0); acc_u4(a, v1); acc_u4(a, v2); acc_u4(a, v3);
        acc_u4(a, v4); acc_u4(a, v5); acc_u4(a, v6); acc_u4(a, v7);
    }
    for (; i + 4 <= e; i += 4) {
        int4 c = *(const int4*)&g_col[i];
        uint4 v0 = ynb[(long)c.x * 32 + lane];
        uint4 v1 = ynb[(long)c.y * 32 + lane];
        uint4 v2 = ynb[(long)c.z * 32 + lane];
        uint4 v3 = ynb[(long)c.w * 32 + lane];
        acc_u4(a, v0); acc_u4(a, v1); acc_u4(a, v2); acc_u4(a, v3);
    }
    for (; i < e; i++) {
        int c = __ldg(&g_col[i]);
        acc_u4(a, ynb[(long)c * 32 + lane]);
    }

    float d = g_invdeg[n];
    long base = (long)n * 64 + lane * 2;
    #pragma unroll
    for (int half = 0; half < 2; half++) {
        float4 sv = ys[base + half];
        float4 r;
        r.x = sv.x + a[half * 4 + 0] * d;
        r.y = sv.y + a[half * 4 + 1] * d;
        r.z = sv.z + a[half * 4 + 2] * d;
        r.w = sv.w + a[half * 4 + 3] * d;
        if (RELU) {
            r.x = fmaxf(r.x, 0.f); r.y = fmaxf(r.y, 0.f);
            r.z = fmaxf(r.z, 0.f); r.w = fmaxf(r.w, 0.f);
        }
        out[base + half] = r;
    }
}

// ---------------- tf32 tensor-core GEMM (round-13, FROZEN) --------------------
// Ys = A@Wself + b (fp32), Yn = A@Wneigh (bf16 if BF16N else fp32).
// BM=128, BK=16, BN=128/64, NOUT compile-time. 8 warps = 2(m) x 4(n).
// A in smem row-major [row][k] (stride 20), B TRANSPOSED [n][k] (stride 20).
// A frag = 1 ldmatrix.x4 per (mt,ks); B frag = 1 ldmatrix.x2 per (nt,ks).

__device__ __forceinline__ float f2tf32(float x) {
    unsigned r;
    asm("cvt.rna.tf32.f32 %0, %1;" : "=r"(r) : "f"(x));
    return __uint_as_float(r);
}
__device__ __forceinline__ unsigned pack_bf162(float lo, float hi) {
    unsigned r;
    asm("cvt.rn.bf16x2.f32 %0, %1, %2;" : "=r"(r) : "f"(hi), "f"(lo));
    return r;
}

#define MMA_TF32(d0, d1, d2, d3, a0, a1, a2, a3, b0, b1)                    \
    asm volatile(                                                           \
        "mma.sync.aligned.m16n8k8.row.col.f32.tf32.tf32.f32 "               \
        "{%0,%1,%2,%3}, {%4,%5,%6,%7}, {%8,%9}, {%0,%1,%2,%3};"             \
        : "+f"(d0), "+f"(d1), "+f"(d2), "+f"(d3)                            \
        : "r"(a0), "r"(a1), "r"(a2), "r"(a3), "r"(b0), "r"(b1))

#define LDSM_X4(d0, d1, d2, d3, addr)                                       \
    asm volatile("ldmatrix.sync.aligned.m8n8.x4.shared.b16 {%0,%1,%2,%3}, [%4];" \
        : "=r"(d0), "=r"(d1), "=r"(d2), "=r"(d3) : "r"(addr))

#define LDSM_X2(d0, d1, addr)                                               \
    asm volatile("ldmatrix.sync.aligned.m8n8.x2.shared.b16 {%0,%1}, [%2];"  \
        : "=r"(d0), "=r"(d1) : "r"(addr))

template<int BN, int NOUT, bool BF16N>
__global__ __launch_bounds__(256, 2) void gemm_tc(
    const float* __restrict__ A,
    const float* __restrict__ Wself, const float* __restrict__ Wneigh,
    const float* __restrict__ bias,
    float* __restrict__ Ys, float* __restrict__ YnF,
    __nv_bfloat16* __restrict__ YnB,
    int M)
{
    constexpr int BM = 128, BK = 16;
    constexpr int APAD = 20;               // A row stride (floats)
    constexpr int BKP  = 20;               // BsT row stride (floats)
    constexpr int NT   = BN / 32;          // n-tiles per warp
    constexpr int BIT  = BN / 64;          // B (n,kgroup) iters per thread
    constexpr int ABYTES = BM * APAD * 4;
    constexpr int BBYTES = BN * BKP * 4;

    __shared__ float As[2][BM * APAD];
    __shared__ float BsT[2][BN * BKP];

    int tid  = threadIdx.x;
    int wid  = tid >> 5;
    int lane = tid & 31;
    int wm = wid >> 2;
    int wn = wid & 3;
    int lr = lane >> 2;
    int lc = lane & 3;
    int bm = blockIdx.x * BM;

    constexpr int tilesPerHalf = NOUT / BN;
    int sel = blockIdx.y / tilesPerHalf;           // 0: self, 1: neigh
    int bn  = (blockIdx.y % tilesPerHalf) * BN;
    const float* W = sel ? Wneigh : Wself;

    float acc[4][NT][4];
    #pragma unroll
    for (int mt = 0; mt < 4; mt++)
        #pragma unroll
        for (int nt = 0; nt < NT; nt++)
            #pragma unroll
            for (int r = 0; r < 4; r++) acc[mt][nt][r] = 0.f;

    // A-tile load/store coords (2 float4 per thread)
    int aRow[2], aKq[2];
    #pragma unroll
    for (int it = 0; it < 2; it++) {
        int idx = tid + it * 256;
        aRow[it] = idx >> 2;
        aKq[it]  = (idx & 3) * 4;
    }
    // B-tile coords: thread handles (n, kgroup) pairs; 4 k-values each
    int bN[BIT], bKg[BIT];
    #pragma unroll
    for (int it = 0; it < BIT; it++) {
        int linear = tid + it * 256;
        bN[it]  = linear % BN;
        bKg[it] = linear / BN;     // 0..3
    }

    // ldmatrix shared-memory byte addresses (per mt / nt, + ks*32 per half)
    unsigned asBase = (unsigned)__cvta_generic_to_shared(&As[0][0]);
    unsigned bsBase = (unsigned)__cvta_generic_to_shared(&BsT[0][0]);
    unsigned aOffB[4], bOffB[NT];
    #pragma unroll
    for (int mt = 0; mt < 4; mt++)
        aOffB[mt] = (unsigned)(((wm * 64 + mt * 16 + (lane & 15)) * APAD
                                + 4 * (lane >> 4)) * 4);
    #pragma unroll
    for (int nt = 0; nt < NT; nt++)
        bOffB[nt] = (unsigned)(((wn * (BN / 4) + nt * 8 + (lane & 7)) * BKP
                                + 4 * ((lane >> 3) & 1)) * 4);

    float4 aR[2];
    float  bV[BIT][4];
    auto loadRegs = [&](int t) {
        int k0 = t * BK;
        #pragma unroll
        for (int it = 0; it < 2; it++) {
            int grow = bm + aRow[it];
            aR[it] = (grow < M)
                ? *(const float4*)(A + (long)grow * F + k0 + aKq[it])
                : make_float4(0.f, 0.f, 0.f, 0.f);
        }
        #pragma unroll
        for (int it = 0; it < BIT; it++)
            #pragma unroll
            for (int j = 0; j < 4; j++)
                bV[it][j] = W[(long)(k0 + bKg[it] * 4 + j) * NOUT + bn + bN[it]];
    };
    auto storeSmem = [&](int p) {
        #pragma unroll
        for (int it = 0; it < 2; it++) {
            float4 v;
            v.x = f2tf32(aR[it].x); v.y = f2tf32(aR[it].y);
            v.z = f2tf32(aR[it].z); v.w = f2tf32(aR[it].w);
            *(float4*)&As[p][aRow[it] * APAD + aKq[it]] = v;
        }
        #pragma unroll
        for (int it = 0; it < BIT; it++) {
            float4 v;
            v.x = f2tf32(bV[it][0]); v.y = f2tf32(bV[it][1]);
            v.z = f2tf32(bV[it][2]); v.w = f2tf32(bV[it][3]);
            *(float4*)&BsT[p][bN[it] * BKP + bKg[it] * 4] = v;
        }
    };

    loadRegs(0);
    storeSmem(0);
    __syncthreads();

    for (int t = 0; t < 16; t++) {
        int p = t & 1;
        if (t < 15) loadRegs(t + 1);
        unsigned aBuf = asBase + p * ABYTES;
        unsigned bBuf = bsBase + p * BBYTES;
        #pragma unroll
        for (int ks = 0; ks < 2; ks++) {
            unsigned af[4][4];
            #pragma unroll
            for (int mt = 0; mt < 4; mt++)
                LDSM_X4(af[mt][0], af[mt][1], af[mt][2], af[mt][3],
                        aBuf + aOffB[mt] + ks * 32);
            unsigned bf[NT][2];
            #pragma unroll
            for (int nt = 0; nt < NT; nt++)
                LDSM_X2(bf[nt][0], bf[nt][1], bBuf + bOffB[nt] + ks * 32);
            #pragma unroll
            for (int mt = 0; mt < 4; mt++)
                #pragma unroll
                for (int nt = 0; nt < NT; nt++)
                    MMA_TF32(acc[mt][nt][0], acc[mt][nt][1],
                             acc[mt][nt][2], acc[mt][nt][3],
                             af[mt][0], af[mt][1], af[mt][2], af[mt][3],
                             bf[nt][0], bf[nt][1]);
        }
        if (t < 15) storeSmem(p ^ 1);
        __syncthreads();
    }

    // epilogue: self half -> fp32 Ys (+bias); neigh half -> bf16 or fp32 Yn
    #pragma unroll
    for (int nt = 0; nt < NT; nt++) {
        int gcol = bn + wn * (BN / 4) + nt * 8 + 2 * lc;
        if (sel == 0) {
            float2 bb = *(const float2*)(bias + gcol);
            #pragma unroll
            for (int mt = 0; mt < 4; mt++) {
                int row0 = bm + wm * 64 + mt * 16 + lr;
                float2 v0, v1;
                v0.x = acc[mt][nt][0] + bb.x;  v0.y = acc[mt][nt][1] + bb.y;
                v1.x = acc[mt][nt][2] + bb.x;  v1.y = acc[mt][nt][3] + bb.y;
                if (row0 < M)     *(float2*)(Ys + (long)row0 * NOUT + gcol) = v0;
                if (row0 + 8 < M) *(float2*)(Ys + (long)(row0 + 8) * NOUT + gcol) = v1;
            }
        } else {
            #pragma unroll
            for (int mt = 0; mt < 4; mt++) {
                int row0 = bm + wm * 64 + mt * 16 + lr;
                if (BF16N) {
                    unsigned p0 = pack_bf162(acc[mt][nt][0], acc[mt][nt][1]);
                    unsigned p1 = pack_bf162(acc[mt][nt][2], acc[mt][nt][3]);
                    if (row0 < M)
                        *(unsigned*)(YnB + (long)row0 * NOUT + gcol) = p0;
                    if (row0 + 8 < M)
                        *(unsigned*)(YnB + (long)(row0 + 8) * NOUT + gcol) = p1;
                } else {
                    float2 v0 = make_float2(acc[mt][nt][0], acc[mt][nt][1]);
                    float2 v1 = make_float2(acc[mt][nt][2], acc[mt][nt][3]);
                    if (row0 < M)     *(float2*)(YnF + (long)row0 * NOUT + gcol) = v0;
                    if (row0 + 8 < M) *(float2*)(YnF + (long)(row0 + 8) * NOUT + gcol) = v1;
                }
            }
        }
    }
}

// ---------------- launch ------------------------------------------------------
extern "C" void kernel_launch(void* const* d_in, const int* in_sizes, int n_in,
                              void* d_out, int out_size) {
    const float* x   = (const float*)d_in[0];
    const int*   src = (const int*)d_in[1];
    const int*   dst = (const int*)d_in[2];
    const float* Ws0 = (const float*)d_in[3];
    const float* Wn0 = (const float*)d_in[4];
    const float* b0  = (const float*)d_in[5];
    const float* Ws1 = (const float*)d_in[6];
    const float* Wn1 = (const float*)d_in[7];
    const float* b1  = (const float*)d_in[8];
    const float* Ws2 = (const float*)d_in[9];
    const float* Wn2 = (const float*)d_in[10];
    const float* b2  = (const float*)d_in[11];

    float* out     = (float*)d_out;
    float* h_final = out;                          // [N, 64]  (tuple elem 0)
    float* h2      = out + (long)N_NODES * OUTF;   // [N, 256] (tuple elem 1)

    float* h1;  float* ys;  float* yn;  __nv_bfloat16* ynb;  int* degp;
    cudaGetSymbolAddress((void**)&h1,  g_h1);
    cudaGetSymbolAddress((void**)&ys,  g_ys);
    cudaGetSymbolAddress((void**)&yn,  g_yn);
    cudaGetSymbolAddress((void**)&ynb, g_ynb);
    cudaGetSymbolAddress((void**)&degp, g_deg);

    dim3 g256((N_NODES + 127) / 128, 4);   // BN=128, NOUT=256: 2 tiles x 2 halves
    dim3 g64((N_NODES + 127) / 128, 2);    // BN=64,  NOUT=64:  1 tile  x 2 halves
    int spmmB = (N_NODES + 7) / 8;

    // ---- fork: CSR build overlaps the (independent) layer-0 GEMM ----
    cudaStream_t s2;
    cudaStreamCreateWithFlags(&s2, cudaStreamNonBlocking);
    cudaEvent_t evFork, evJoin;
    cudaEventCreateWithFlags(&evFork, cudaEventDisableTiming);
    cudaEventCreateWithFlags(&evJoin, cudaEventDisableTiming);

    cudaEventRecord(evFork, 0);
    cudaStreamWaitEvent(s2, evFork, 0);
    cudaMemsetAsync(degp, 0, N_NODES * sizeof(int), s2);
    count_kernel<<<(N_EDGES + 255) / 256, 256, 0, s2>>>(dst);
    scan_kernel<<<1, 1024, 0, s2>>>();
    fill_kernel<<<(N_EDGES + 255) / 256, 256, 0, s2>>>(src, dst);
    cudaEventRecord(evJoin, s2);

    // layer-0 GEMM on main stream (does not need the CSR)
    gemm_tc<128, 256, true><<<g256, 256>>>(x, Ws0, Wn0, b0, ys, yn, ynb, N_NODES);

    // join: SPMM needs both the CSR and the GEMM outputs
    cudaStreamWaitEvent(0, evJoin, 0);
    spmm_bf16_kernel<true><<<spmmB, 256>>>(
        (const uint4*)ynb, (const float4*)ys, (float4*)h1);
    // layer 1 (output doubles as tuple elem 1)
    gemm_tc<128, 256, true><<<g256, 256>>>(h1, Ws1, Wn1, b1, ys, yn, ynb, N_NODES);
    spmm_bf16_kernel<true><<<spmmB, 256>>>(
        (const uint4*)ynb, (const float4*)ys, (float4*)h2);
    // layer 2 (64-dim fp32 aggregation, no relu)
    gemm_tc<64, 64, false><<<g64, 256>>>(h2, Ws2, Wn2, b2, ys, yn, ynb, N_NODES);
    spmm_add_kernel<16, false><<<(N_NODES + 15) / 16, 256>>>(
        (const float4*)yn, (const float4*)ys, (float4*)h_final);

    cudaStreamDestroy(s2);
    cudaEventDestroy(evFork);
    cudaEventDestroy(evJoin);
}

// round 17
// speedup vs baseline: 1.0256x; 1.0256x over previous
#include <cuda_runtime.h>
#include <cuda_bf16.h>
#include <stdint.h>

#define N_NODES 50000
#define N_EDGES 1600000
#define F 256
#define OUTF 64

// ---------------- scratch (static device globals; no runtime alloc) ----------
__device__ float g_h1[(long)N_NODES * F];    // layer-0 output
__device__ float g_ys[(long)N_NODES * F];    // self-term buffer
__device__ __nv_bfloat16 g_ynb[(long)N_NODES * F];  // neighbor-term bf16 (all layers)
__device__ int   g_rowptr[N_NODES + 1];
__device__ int   g_cursor[N_NODES];
__device__ int   g_col[N_EDGES];
__device__ int   g_deg[N_NODES];
__device__ float g_invdeg[N_NODES];

// ---------------- CSR build ---------------------------------------------------
__global__ void count_kernel(const int* __restrict__ dst) {
    int e = blockIdx.x * blockDim.x + threadIdx.x;
    if (e < N_EDGES) atomicAdd(&g_deg[dst[e]], 1);
}

__global__ __launch_bounds__(1024) void scan_kernel() {
    __shared__ int sm[1024];
    const int CH = (N_NODES + 1023) / 1024;
    int tid = threadIdx.x;
    int start = tid * CH;
    int end = min(start + CH, N_NODES);
    int local = 0;
    for (int i = start; i < end; i++) local += g_deg[i];
    sm[tid] = local;
    __syncthreads();
    #pragma unroll
    for (int off = 1; off < 1024; off <<= 1) {
        int t = (tid >= off) ? sm[tid - off] : 0;
        __syncthreads();
        sm[tid] += t;
        __syncthreads();
    }
    int run = sm[tid] - local;
    for (int i = start; i < end; i++) {
        int v = g_deg[i];
        g_rowptr[i] = run;
        g_cursor[i] = run;
        g_invdeg[i] = 1.0f / (float)max(v, 1);
        run += v;
    }
    if (tid == 0) g_rowptr[N_NODES] = sm[1023];
}

__global__ void fill_kernel(const int* __restrict__ src, const int* __restrict__ dst) {
    int e = blockIdx.x * blockDim.x + threadIdx.x;
    if (e < N_EDGES) {
        int d = dst[e];
        int p = atomicAdd(&g_cursor[d], 1);
        g_col[p] = src[e];
    }
}

// ---------------- SpMM bf16 gather: out = relu?(ys + invdeg * sum ynb[src]) ---
// LU4 = uint4 lanes per node row. 256-dim: LU4=32 (512B). 64-dim: LU4=8 (128B).
// Each thread accumulates 8 bf16 values (1 uint4). Round-13 4-deep body.
__device__ __forceinline__ void acc_bf16x2(float* a, unsigned u) {
    a[0] += __uint_as_float(u << 16);
    a[1] += __uint_as_float(u & 0xffff0000u);
}
__device__ __forceinline__ void acc_u4(float* a, uint4 v) {
    acc_bf16x2(a + 0, v.x);
    acc_bf16x2(a + 2, v.y);
    acc_bf16x2(a + 4, v.z);
    acc_bf16x2(a + 6, v.w);
}

template<int LU4, bool RELU>
__global__ __launch_bounds__(256) void spmm_bf16_kernel(
    const uint4* __restrict__ ynb, const float4* __restrict__ ys,
    float4* __restrict__ out)
{
    constexpr int NPB = 256 / LU4;
    int group = threadIdx.x / LU4;
    int lane  = threadIdx.x % LU4;      // LU4 x 16B = feature row bytes
    int n = blockIdx.x * NPB + group;
    if (n >= N_NODES) return;
    int s = g_rowptr[n];
    int e = g_rowptr[n + 1];

    float a[8];
    #pragma unroll
    for (int j = 0; j < 8; j++) a[j] = 0.f;

    int i = s;
    int alignEnd = min(e, (s + 3) & ~3);
    for (; i < alignEnd; i++) {
        int c = __ldg(&g_col[i]);
        acc_u4(a, ynb[(long)c * LU4 + lane]);
    }
    for (; i + 4 <= e; i += 4) {
        int4 c = *(const int4*)&g_col[i];
        uint4 v0 = ynb[(long)c.x * LU4 + lane];
        uint4 v1 = ynb[(long)c.y * LU4 + lane];
        uint4 v2 = ynb[(long)c.z * LU4 + lane];
        uint4 v3 = ynb[(long)c.w * LU4 + lane];
        acc_u4(a, v0); acc_u4(a, v1); acc_u4(a, v2); acc_u4(a, v3);
    }
    for (; i < e; i++) {
        int c = __ldg(&g_col[i]);
        acc_u4(a, ynb[(long)c * LU4 + lane]);
    }

    float d = g_invdeg[n];
    long base = (long)n * (LU4 * 2) + lane * 2;   // float4 index (8 floats/lane)
    #pragma unroll
    for (int half = 0; half < 2; half++) {
        float4 sv = ys[base + half];
        float4 r;
        r.x = sv.x + a[half * 4 + 0] * d;
        r.y = sv.y + a[half * 4 + 1] * d;
        r.z = sv.z + a[half * 4 + 2] * d;
        r.w = sv.w + a[half * 4 + 3] * d;
        if (RELU) {
            r.x = fmaxf(r.x, 0.f); r.y = fmaxf(r.y, 0.f);
            r.z = fmaxf(r.z, 0.f); r.w = fmaxf(r.w, 0.f);
        }
        out[base + half] = r;
    }
}

// ---------------- tf32 tensor-core GEMM (round-13, FROZEN) --------------------
// Ys = A@Wself + b (fp32), Yn = A@Wneigh -> bf16.
// BM=128, BK=16, BN=128/64, NOUT compile-time. 8 warps = 2(m) x 4(n).
// A in smem row-major [row][k] (stride 20), B TRANSPOSED [n][k] (stride 20).
// A frag = 1 ldmatrix.x4 per (mt,ks); B frag = 1 ldmatrix.x2 per (nt,ks).

__device__ __forceinline__ float f2tf32(float x) {
    unsigned r;
    asm("cvt.rna.tf32.f32 %0, %1;" : "=r"(r) : "f"(x));
    return __uint_as_float(r);
}
__device__ __forceinline__ unsigned pack_bf162(float lo, float hi) {
    unsigned r;
    asm("cvt.rn.bf16x2.f32 %0, %1, %2;" : "=r"(r) : "f"(hi), "f"(lo));
    return r;
}

#define MMA_TF32(d0, d1, d2, d3, a0, a1, a2, a3, b0, b1)                    \
    asm volatile(                                                           \
        "mma.sync.aligned.m16n8k8.row.col.f32.tf32.tf32.f32 "               \
        "{%0,%1,%2,%3}, {%4,%5,%6,%7}, {%8,%9}, {%0,%1,%2,%3};"             \
        : "+f"(d0), "+f"(d1), "+f"(d2), "+f"(d3)                            \
        : "r"(a0), "r"(a1), "r"(a2), "r"(a3), "r"(b0), "r"(b1))

#define LDSM_X4(d0, d1, d2, d3, addr)                                       \
    asm volatile("ldmatrix.sync.aligned.m8n8.x4.shared.b16 {%0,%1,%2,%3}, [%4];" \
        : "=r"(d0), "=r"(d1), "=r"(d2), "=r"(d3) : "r"(addr))

#define LDSM_X2(d0, d1, addr)                                               \
    asm volatile("ldmatrix.sync.aligned.m8n8.x2.shared.b16 {%0,%1}, [%2];"  \
        : "=r"(d0), "=r"(d1) : "r"(addr))

template<int BN, int NOUT>
__global__ __launch_bounds__(256, 2) void gemm_tc(
    const float* __restrict__ A,
    const float* __restrict__ Wself, const float* __restrict__ Wneigh,
    const float* __restrict__ bias,
    float* __restrict__ Ys, __nv_bfloat16* __restrict__ YnB,
    int M)
{
    constexpr int BM = 128, BK = 16;
    constexpr int APAD = 20;               // A row stride (floats)
    constexpr int BKP  = 20;               // BsT row stride (floats)
    constexpr int NT   = BN / 32;          // n-tiles per warp
    constexpr int BIT  = BN / 64;          // B (n,kgroup) iters per thread
    constexpr int ABYTES = BM * APAD * 4;
    constexpr int BBYTES = BN * BKP * 4;

    __shared__ float As[2][BM * APAD];
    __shared__ float BsT[2][BN * BKP];

    int tid  = threadIdx.x;
    int wid  = tid >> 5;
    int lane = tid & 31;
    int wm = wid >> 2;
    int wn = wid & 3;
    int lr = lane >> 2;
    int lc = lane & 3;
    int bm = blockIdx.x * BM;

    constexpr int tilesPerHalf = NOUT / BN;
    int sel = blockIdx.y / tilesPerHalf;           // 0: self, 1: neigh
    int bn  = (blockIdx.y % tilesPerHalf) * BN;
    const float* W = sel ? Wneigh : Wself;

    float acc[4][NT][4];
    #pragma unroll
    for (int mt = 0; mt < 4; mt++)
        #pragma unroll
        for (int nt = 0; nt < NT; nt++)
            #pragma unroll
            for (int r = 0; r < 4; r++) acc[mt][nt][r] = 0.f;

    // A-tile load/store coords (2 float4 per thread)
    int aRow[2], aKq[2];
    #pragma unroll
    for (int it = 0; it < 2; it++) {
        int idx = tid + it * 256;
        aRow[it] = idx >> 2;
        aKq[it]  = (idx & 3) * 4;
    }
    // B-tile coords: thread handles (n, kgroup) pairs; 4 k-values each
    int bN[BIT], bKg[BIT];
    #pragma unroll
    for (int it = 0; it < BIT; it++) {
        int linear = tid + it * 256;
        bN[it]  = linear % BN;
        bKg[it] = linear / BN;     // 0..3
    }

    // ldmatrix shared-memory byte addresses (per mt / nt, + ks*32 per half)
    unsigned asBase = (unsigned)__cvta_generic_to_shared(&As[0][0]);
    unsigned bsBase = (unsigned)__cvta_generic_to_shared(&BsT[0][0]);
    unsigned aOffB[4], bOffB[NT];
    #pragma unroll
    for (int mt = 0; mt < 4; mt++)
        aOffB[mt] = (unsigned)(((wm * 64 + mt * 16 + (lane & 15)) * APAD
                                + 4 * (lane >> 4)) * 4);
    #pragma unroll
    for (int nt = 0; nt < NT; nt++)
        bOffB[nt] = (unsigned)(((wn * (BN / 4) + nt * 8 + (lane & 7)) * BKP
                                + 4 * ((lane >> 3) & 1)) * 4);

    float4 aR[2];
    float  bV[BIT][4];
    auto loadRegs = [&](int t) {
        int k0 = t * BK;
        #pragma unroll
        for (int it = 0; it < 2; it++) {
            int grow = bm + aRow[it];
            aR[it] = (grow < M)
                ? *(const float4*)(A + (long)grow * F + k0 + aKq[it])
                : make_float4(0.f, 0.f, 0.f, 0.f);
        }
        #pragma unroll
        for (int it = 0; it < BIT; it++)
            #pragma unroll
            for (int j = 0; j < 4; j++)
                bV[it][j] = W[(long)(k0 + bKg[it] * 4 + j) * NOUT + bn + bN[it]];
    };
    auto storeSmem = [&](int p) {
        #pragma unroll
        for (int it = 0; it < 2; it++) {
            float4 v;
            v.x = f2tf32(aR[it].x); v.y = f2tf32(aR[it].y);
            v.z = f2tf32(aR[it].z); v.w = f2tf32(aR[it].w);
            *(float4*)&As[p][aRow[it] * APAD + aKq[it]] = v;
        }
        #pragma unroll
        for (int it = 0; it < BIT; it++) {
            float4 v;
            v.x = f2tf32(bV[it][0]); v.y = f2tf32(bV[it][1]);
            v.z = f2tf32(bV[it][2]); v.w = f2tf32(bV[it][3]);
            *(float4*)&BsT[p][bN[it] * BKP + bKg[it] * 4] = v;
        }
    };

    loadRegs(0);
    storeSmem(0);
    __syncthreads();

    for (int t = 0; t < 16; t++) {
        int p = t & 1;
        if (t < 15) loadRegs(t + 1);
        unsigned aBuf = asBase + p * ABYTES;
        unsigned bBuf = bsBase + p * BBYTES;
        #pragma unroll
        for (int ks = 0; ks < 2; ks++) {
            unsigned af[4][4];
            #pragma unroll
            for (int mt = 0; mt < 4; mt++)
                LDSM_X4(af[mt][0], af[mt][1], af[mt][2], af[mt][3],
                        aBuf + aOffB[mt] + ks * 32);
            unsigned bf[NT][2];
            #pragma unroll
            for (int nt = 0; nt < NT; nt++)
                LDSM_X2(bf[nt][0], bf[nt][1], bBuf + bOffB[nt] + ks * 32);
            #pragma unroll
            for (int mt = 0; mt < 4; mt++)
                #pragma unroll
                for (int nt = 0; nt < NT; nt++)
                    MMA_TF32(acc[mt][nt][0], acc[mt][nt][1],
                             acc[mt][nt][2], acc[mt][nt][3],
                             af[mt][0], af[mt][1], af[mt][2], af[mt][3],
                             bf[nt][0], bf[nt][1]);
        }
        if (t < 15) storeSmem(p ^ 1);
        __syncthreads();
    }

    // epilogue: self half -> fp32 Ys (+bias); neigh half -> bf16 Yn
    #pragma unroll
    for (int nt = 0; nt < NT; nt++) {
        int gcol = bn + wn * (BN / 4) + nt * 8 + 2 * lc;
        if (sel == 0) {
            float2 bb = *(const float2*)(bias + gcol);
            #pragma unroll
            for (int mt = 0; mt < 4; mt++) {
                int row0 = bm + wm * 64 + mt * 16 + lr;
                float2 v0, v1;
                v0.x = acc[mt][nt][0] + bb.x;  v0.y = acc[mt][nt][1] + bb.y;
                v1.x = acc[mt][nt][2] + bb.x;  v1.y = acc[mt][nt][3] + bb.y;
                if (row0 < M)     *(float2*)(Ys + (long)row0 * NOUT + gcol) = v0;
                if (row0 + 8 < M) *(float2*)(Ys + (long)(row0 + 8) * NOUT + gcol) = v1;
            }
        } else {
            #pragma unroll
            for (int mt = 0; mt < 4; mt++) {
                int row0 = bm + wm * 64 + mt * 16 + lr;
                unsigned p0 = pack_bf162(acc[mt][nt][0], acc[mt][nt][1]);
                unsigned p1 = pack_bf162(acc[mt][nt][2], acc[mt][nt][3]);
                if (row0 < M)
                    *(unsigned*)(YnB + (long)row0 * NOUT + gcol) = p0;
                if (row0 + 8 < M)
                    *(unsigned*)(YnB + (long)(row0 + 8) * NOUT + gcol) = p1;
            }
        }
    }
}

// ---------------- launch ------------------------------------------------------
extern "C" void kernel_launch(void* const* d_in, const int* in_sizes, int n_in,
                              void* d_out, int out_size) {
    const float* x   = (const float*)d_in[0];
    const int*   src = (const int*)d_in[1];
    const int*   dst = (const int*)d_in[2];
    const float* Ws0 = (const float*)d_in[3];
    const float* Wn0 = (const float*)d_in[4];
    const float* b0  = (const float*)d_in[5];
    const float* Ws1 = (const float*)d_in[6];
    const float* Wn1 = (const float*)d_in[7];
    const float* b1  = (const float*)d_in[8];
    const float* Ws2 = (const float*)d_in[9];
    const float* Wn2 = (const float*)d_in[10];
    const float* b2  = (const float*)d_in[11];

    float* out     = (float*)d_out;
    float* h_final = out;                          // [N, 64]  (tuple elem 0)
    float* h2      = out + (long)N_NODES * OUTF;   // [N, 256] (tuple elem 1)

    float* h1;  float* ys;  __nv_bfloat16* ynb;  int* degp;
    cudaGetSymbolAddress((void**)&h1,  g_h1);
    cudaGetSymbolAddress((void**)&ys,  g_ys);
    cudaGetSymbolAddress((void**)&ynb, g_ynb);
    cudaGetSymbolAddress((void**)&degp, g_deg);

    dim3 g256((N_NODES + 127) / 128, 4);   // BN=128, NOUT=256: 2 tiles x 2 halves
    dim3 g64((N_NODES + 127) / 128, 2);    // BN=64,  NOUT=64:  1 tile  x 2 halves
    int spmmB256 = (N_NODES + 7) / 8;      // 8 nodes/block (LU4=32)
    int spmmB64  = (N_NODES + 31) / 32;    // 32 nodes/block (LU4=8)

    // ---- fork: CSR build overlaps the (independent) layer-0 GEMM ----
    cudaStream_t s2;
    cudaStreamCreateWithFlags(&s2, cudaStreamNonBlocking);
    cudaEvent_t evFork, evJoin;
    cudaEventCreateWithFlags(&evFork, cudaEventDisableTiming);
    cudaEventCreateWithFlags(&evJoin, cudaEventDisableTiming);

    cudaEventRecord(evFork, 0);
    cudaStreamWaitEvent(s2, evFork, 0);
    cudaMemsetAsync(degp, 0, N_NODES * sizeof(int), s2);
    count_kernel<<<(N_EDGES + 255) / 256, 256, 0, s2>>>(dst);
    scan_kernel<<<1, 1024, 0, s2>>>();
    fill_kernel<<<(N_EDGES + 255) / 256, 256, 0, s2>>>(src, dst);
    cudaEventRecord(evJoin, s2);

    // layer-0 GEMM on main stream (does not need the CSR)
    gemm_tc<128, 256><<<g256, 256>>>(x, Ws0, Wn0, b0, ys, ynb, N_NODES);

    // join: SPMM needs both the CSR and the GEMM outputs
    cudaStreamWaitEvent(0, evJoin, 0);
    spmm_bf16_kernel<32, true><<<spmmB256, 256>>>(
        (const uint4*)ynb, (const float4*)ys, (float4*)h1);
    // layer 1 (output doubles as tuple elem 1)
    gemm_tc<128, 256><<<g256, 256>>>(h1, Ws1, Wn1, b1, ys, ynb, N_NODES);
    spmm_bf16_kernel<32, true><<<spmmB256, 256>>>(
        (const uint4*)ynb, (const float4*)ys, (float4*)h2);
    // layer 2 (64-dim bf16 aggregation, no relu; LU4=8 -> 128B rows)
    gemm_tc<64, 64><<<g64, 256>>>(h2, Ws2, Wn2, b2, ys, ynb, N_NODES);
    spmm_bf16_kernel<8, false><<<spmmB64, 256>>>(
        (const uint4*)ynb, (const float4*)ys, (float4*)h_final);

    cudaStreamDestroy(s2);
    cudaEventDestroy(evFork);
    cudaEventDestroy(evJoin);
}